// round 1
// baseline (speedup 1.0000x reference)
#include <cuda_runtime.h>
#include <cuda_bf16.h>

// NCE loss, training branch, size_average=True.
// Shapes (fixed for this problem): N=4096, E=1024, V=50257, K=25.
// loss = -(1/N) * sum_n [ log(p0/(p0+k*pn_t)) + sum_{j=1..K} log(k*pn_j/(p_j+k*pn_j)) ]
// with p = exp(b[idx] + x[n].w[idx] - 9).

#define MAX_N 4096
#define THREADS 256
#define NWARP (THREADS / 32)

__device__ float g_partials[MAX_N];

__global__ __launch_bounds__(THREADS, 8)
void nce_main(const float* __restrict__ x,
              const int*   __restrict__ target,
              const int*   __restrict__ noise_idx,
              const float* __restrict__ weight,
              const float* __restrict__ bias,
              const float* __restrict__ noise,
              int E, int K)
{
    const int n    = blockIdx.x;
    const int tid  = threadIdx.x;
    const int lane = tid & 31;
    const int wid  = tid >> 5;

    __shared__ float4 xs[256];     // E = 1024 floats
    __shared__ float  wloss[NWARP];

    // Stage x[n] into shared (one float4 per thread, fully coalesced)
    const float4* x4 = reinterpret_cast<const float4*>(x + (size_t)n * E);
    xs[tid] = x4[tid];
    __syncthreads();

    const int nk = K + 1;          // 26 candidate rows: [target, noise...]
    float loss = 0.0f;

    // Each warp owns k = wid, wid+8, wid+16, ... (3-4 dots per warp).
    for (int k = wid; k < nk; k += NWARP) {
        const int idx = (k == 0) ? target[n] : noise_idx[n * K + (k - 1)];
        const float4* wrow = reinterpret_cast<const float4*>(weight + (size_t)idx * E);

        // 1024-elem dot: 8 independent float4 loads per lane (MLP=8)
        float s = 0.0f;
        #pragma unroll
        for (int j = 0; j < 8; j++) {
            const float4 wv = __ldg(&wrow[lane + 32 * j]);
            const float4 xv = xs[lane + 32 * j];
            s += wv.x * xv.x + wv.y * xv.y + wv.z * xv.z + wv.w * xv.w;
        }
        // Warp-level reduction (no block barrier)
        #pragma unroll
        for (int o = 16; o; o >>= 1)
            s += __shfl_xor_sync(0xffffffffu, s, o);

        if (lane == 0) {
            const float logit = s + __ldg(&bias[idx]);
            const float p     = __expf(logit - 9.0f);
            const float kpn   = 25.0f * __ldg(&noise[idx]);
            // k==0: data term log(p/(p+kpn)); else noise term log(kpn/(p+kpn))
            const float num   = (k == 0) ? p : kpn;
            loss += __logf(num / (p + kpn));
        }
    }

    if (lane == 0) wloss[wid] = loss;
    __syncthreads();

    if (tid == 0) {
        float t = 0.0f;
        #pragma unroll
        for (int w = 0; w < NWARP; w++) t += wloss[w];
        g_partials[n] = t;   // deterministic per-row partial
    }
}

__global__ void nce_reduce(float* __restrict__ out, int N)
{
    __shared__ float sh[1024];
    const int tid = threadIdx.x;
    float s = 0.0f;
    for (int i = tid; i < N; i += 1024) s += g_partials[i];
    sh[tid] = s;
    __syncthreads();
    #pragma unroll
    for (int o = 512; o; o >>= 1) {
        if (tid < o) sh[tid] += sh[tid + o];
        __syncthreads();
    }
    if (tid == 0) out[0] = -sh[0] / (float)N;
}

extern "C" void kernel_launch(void* const* d_in, const int* in_sizes, int n_in,
                              void* d_out, int out_size)
{
    const float* x         = (const float*)d_in[0];
    const int*   target    = (const int*)  d_in[1];
    const int*   noise_idx = (const int*)  d_in[2];
    const float* weight    = (const float*)d_in[3];
    const float* bias      = (const float*)d_in[4];
    const float* noise     = (const float*)d_in[5];

    const int N = in_sizes[1];            // 4096
    const int E = in_sizes[0] / N;        // 1024
    const int K = in_sizes[2] / N;        // 25

    nce_main<<<N, THREADS>>>(x, target, noise_idx, weight, bias, noise, E, K);
    nce_reduce<<<1, 1024>>>((float*)d_out, N);
}